// round 12
// baseline (speedup 1.0000x reference)
#include <cuda_runtime.h>
#include <math.h>
#include <float.h>

#define MAXN      (1 << 20)   // dist scratch capacity (N = 1e6 fits)
#define CAND_CAP  65536
#define KSEL      32
#define NBINS     8192        // coarse bins = float_bits(d) >> 18 (monotone, d >= 0)
#define BSHIFT    18
#define FSHIFT    8           // fine bins: 256-ulp wide, 1024 per coarse bin
#define NFINE     1024
#define MAXBLK    4096
#define SORT_CAP  2048        // final bitonic capacity (u64 keys, 16 KB)

// ---- scratch (static device globals; zero-initialized at module load) ----
__device__ float              g_dist[MAXN];
__device__ float              g_partsum[MAXBLK];
__device__ unsigned           g_hist[NBINS];   // reset by k_final
__device__ float              g_Z;
__device__ int                g_bin_thresh;
__device__ int                g_ncand;         // reset by k_final
__device__ unsigned long long g_cand[CAND_CAP];
__device__ unsigned           g_done1;         // reset by k_dist last block

// ============================================================================
// Kernel 1: distances (coalesced, 16 rows/warp-iter), exp-sum partials,
// 16-bit-packed shared histogram. Last block: Z reduce + coarse threshold bin.
// ============================================================================
__global__ void k_dist(const float* __restrict__ X, const float* __restrict__ q,
                       int N, int D) {
    __shared__ unsigned hist16[NBINS / 2];   // 16 KB packed block histogram
    __shared__ float4   sq4[16];
    __shared__ float    red[256];
    __shared__ unsigned chunk[256];          // 32 coarse bins each
    __shared__ unsigned super[32];           // 8 chunks each
    __shared__ unsigned binv[32];
    __shared__ int      sel_chunk;
    __shared__ unsigned cum_at_chunk;
    __shared__ bool     amLast;

    int tid = threadIdx.x;
    for (int i = tid; i < NBINS / 2; i += 256) hist16[i] = 0u;
    if (D == 64 && tid < 16) sq4[tid] = ((const float4*)q)[tid];
    __syncthreads();

    float lsum = 0.0f;

    if (D == 64) {
        int lane = tid & 31;
        int wid  = blockIdx.x * (blockDim.x >> 5) + (tid >> 5);
        int nw   = gridDim.x * (blockDim.x >> 5);
        int col  = lane & 15;      // 16 lanes cover one 64-float row
        int half = lane >> 4;      // two rows per LDG.128
        float4 qv = sq4[col];

        for (int base = wid * 16; base < N; base += nw * 16) {
            float4 v[8];
            float  acc[8];
            #pragma unroll
            for (int u = 0; u < 8; u++) {          // 8 loads batched in flight
                int row = base + 2 * u + half;
                v[u] = qv;                          // OOB => zero diff (unused)
                if (row < N)
                    v[u] = *(const float4*)(X + (size_t)row * 64 + col * 4);
            }
            #pragma unroll
            for (int u = 0; u < 8; u++) {
                float d0 = v[u].x - qv.x, d1 = v[u].y - qv.y;
                float d2 = v[u].z - qv.z, d3 = v[u].w - qv.w;
                acc[u] = d0 * d0 + d1 * d1 + d2 * d2 + d3 * d3;
            }
            #pragma unroll
            for (int u = 0; u < 8; u++) {          // independent shfl chains
                acc[u] += __shfl_xor_sync(0xffffffffu, acc[u], 8);
                acc[u] += __shfl_xor_sync(0xffffffffu, acc[u], 4);
                acc[u] += __shfl_xor_sync(0xffffffffu, acc[u], 2);
                acc[u] += __shfl_xor_sync(0xffffffffu, acc[u], 1);
            }
            if (col == 0) {
                #pragma unroll
                for (int u = 0; u < 8; u++) {
                    int row = base + 2 * u + half;
                    if (row < N) {
                        float d = sqrtf(acc[u]);
                        g_dist[row] = d;
                        lsum += expf(-d);           // TAU = 1
                        unsigned b = __float_as_uint(d) >> BSHIFT;
                        atomicAdd(&hist16[b >> 1], 1u << ((b & 1) * 16));
                    }
                }
            }
        }
    } else {
        for (int i = blockIdx.x * blockDim.x + tid; i < N;
             i += gridDim.x * blockDim.x) {
            float acc = 0.0f;
            const float* xr = X + (size_t)i * D;
            for (int j = 0; j < D; j++) { float d = xr[j] - q[j]; acc += d * d; }
            float d = sqrtf(acc);
            g_dist[i] = d;
            lsum += expf(-d);
            unsigned b = __float_as_uint(d) >> BSHIFT;
            atomicAdd(&hist16[b >> 1], 1u << ((b & 1) * 16));
        }
    }

    // block Z partial (deterministic)
    red[tid] = lsum;
    __syncthreads();
    for (int s = 128; s > 0; s >>= 1) {
        if (tid < s) red[tid] += red[tid + s];
        __syncthreads();
    }
    if (tid == 0) g_partsum[blockIdx.x] = red[0];

    // flush packed histogram
    for (int i = tid; i < NBINS / 2; i += 256) {
        unsigned v = hist16[i];
        unsigned lo = v & 0xffffu, hi = v >> 16;
        if (lo) atomicAdd(&g_hist[2 * i],     lo);
        if (hi) atomicAdd(&g_hist[2 * i + 1], hi);
    }

    // ---- last-block tail ----
    __threadfence();
    if (tid == 0) amLast = (atomicAdd(&g_done1, 1u) == (unsigned)gridDim.x - 1u);
    __syncthreads();
    if (!amLast) return;

    float s2 = 0.0f;
    for (int i = tid; i < gridDim.x; i += 256) s2 += g_partsum[i];
    red[tid] = s2;
    __syncthreads();
    for (int s = 128; s > 0; s >>= 1) {
        if (tid < s) red[tid] += red[tid + s];
        __syncthreads();
    }
    if (tid == 0) g_Z = red[0];

    // 3-level coarse threshold scan: chunk(32 bins) -> super(8 chunks) -> bins
    unsigned cs = 0;
    for (int j = 0; j < 32; j++) cs += g_hist[tid * 32 + j];
    chunk[tid] = cs;
    __syncthreads();
    if (tid < 32) {
        unsigned s = 0;
        #pragma unroll
        for (int j = 0; j < 8; j++) s += chunk[tid * 8 + j];
        super[tid] = s;
    }
    __syncthreads();
    if (tid == 0) {
        unsigned target = (unsigned)(N < KSEL ? N : KSEL);
        unsigned cum = 0;
        int si = 0;
        while (si < 31 && cum + super[si] < target) { cum += super[si]; si++; }
        int c = si * 8;
        while (c < si * 8 + 7 && cum + chunk[c] < target) { cum += chunk[c]; c++; }
        sel_chunk = c;
        cum_at_chunk = cum;
    }
    __syncthreads();
    if (tid < 32) binv[tid] = g_hist[sel_chunk * 32 + tid];
    __syncthreads();
    if (tid == 0) {
        unsigned target = (unsigned)(N < KSEL ? N : KSEL);
        unsigned cum = cum_at_chunk;
        int b = sel_chunk * 32;
        int j = 0;
        while (j < 31 && cum + binv[j] < target) { cum += binv[j]; j++; b++; }
        if (b >= NBINS) b = NBINS - 1;
        g_bin_thresh = b;
        g_done1 = 0;                 // reset for next graph replay
    }
}

// ============================================================================
// Kernel 2: lean candidate compaction. 4 batched LDG.128 per thread, packed
// u64 key append. No tail code => low regs => high occupancy.
// ============================================================================
__global__ void k_compact(int N) {
    int tid = blockIdx.x * blockDim.x + threadIdx.x;
    int stride = gridDim.x * blockDim.x;
    unsigned limit = ((unsigned)(g_bin_thresh + 1)) << BSHIFT;
    const float4* d4 = (const float4*)g_dist;
    int n4 = N >> 2;

    int i0 = tid, i1 = tid + stride, i2 = tid + 2 * stride, i3 = tid + 3 * stride;
    float4 z = make_float4(FLT_MAX, FLT_MAX, FLT_MAX, FLT_MAX);
    float4 v0 = (i0 < n4) ? d4[i0] : z;
    float4 v1 = (i1 < n4) ? d4[i1] : z;
    float4 v2 = (i2 < n4) ? d4[i2] : z;
    float4 v3 = (i3 < n4) ? d4[i3] : z;

    #define CHECK(vv, ii, cc) do {                                             \
        unsigned bits_ = __float_as_uint(vv);                                  \
        if (bits_ < limit) {                                                   \
            int p_ = atomicAdd(&g_ncand, 1);                                   \
            if (p_ < CAND_CAP)                                                 \
                g_cand[p_] = ((unsigned long long)bits_ << 32) |               \
                             (unsigned)(4 * (ii) + (cc));                      \
        }                                                                      \
    } while (0)

    if (i0 < n4) { CHECK(v0.x, i0, 0); CHECK(v0.y, i0, 1); CHECK(v0.z, i0, 2); CHECK(v0.w, i0, 3); }
    if (i1 < n4) { CHECK(v1.x, i1, 0); CHECK(v1.y, i1, 1); CHECK(v1.z, i1, 2); CHECK(v1.w, i1, 3); }
    if (i2 < n4) { CHECK(v2.x, i2, 0); CHECK(v2.y, i2, 1); CHECK(v2.z, i2, 2); CHECK(v2.w, i2, 3); }
    if (i3 < n4) { CHECK(v3.x, i3, 0); CHECK(v3.y, i3, 1); CHECK(v3.z, i3, 2); CHECK(v3.w, i3, 3); }
    #undef CHECK

    if (tid == 0) {                                  // scalar tail (N % 4)
        for (int i = n4 * 4; i < N; i++) {
            unsigned bits = __float_as_uint(g_dist[i]);
            if (bits < limit) {
                int p = atomicAdd(&g_ncand, 1);
                if (p < CAND_CAP)
                    g_cand[p] = ((unsigned long long)bits << 32) | (unsigned)i;
            }
        }
    }
}

// ============================================================================
// Kernel 3: single block. Fine refinement (exact 256-ulp threshold) ->
// tiny bitonic sort -> weights/output -> scratch reset.
// ============================================================================
__global__ void k_final(const float* __restrict__ y, float* __restrict__ out,
                        int N, int DY) {
    __shared__ unsigned long long skey[SORT_CAP];   // 16 KB
    __shared__ unsigned fine[NFINE];                // 4 KB
    __shared__ unsigned fchunk[256];
    __shared__ unsigned fsuper[32];
    __shared__ int      s_below, s_cnt2;
    __shared__ unsigned s_limit2;
    __shared__ float    w[KSEL];
    __shared__ int      widx[KSEL];
    __shared__ float    gred[256];

    int tid = threadIdx.x;
    int bt = g_bin_thresh;
    float Z = g_Z;

    if (tid == 0) { s_below = 0; s_cnt2 = 0; }
    for (int i = tid; i < NFINE; i += 256) fine[i] = 0u;
    __syncthreads();

    int ncand = g_ncand;
    if (ncand > CAND_CAP) ncand = CAND_CAP;
    unsigned base = ((unsigned)bt) << BSHIFT;
    unsigned target = (unsigned)(N < KSEL ? N : KSEL);

    // fine histogram of candidates within the coarse threshold bin
    for (int i = tid; i < ncand; i += 256) {
        unsigned bits = (unsigned)(g_cand[i] >> 32);
        if (bits < base) atomicAdd((unsigned*)&s_below, 1u);
        else             atomicAdd(&fine[(bits - base) >> FSHIFT], 1u);
    }
    __syncthreads();

    // 3-level fine prefix
    fchunk[tid] = fine[tid * 4] + fine[tid * 4 + 1] +
                  fine[tid * 4 + 2] + fine[tid * 4 + 3];
    __syncthreads();
    if (tid < 32) {
        unsigned s = 0;
        #pragma unroll
        for (int j = 0; j < 8; j++) s += fchunk[tid * 8 + j];
        fsuper[tid] = s;
    }
    __syncthreads();
    if (tid == 0) {
        unsigned cum = (unsigned)s_below;
        int si = 0;
        while (si < 31 && cum + fsuper[si] < target) { cum += fsuper[si]; si++; }
        int c = si * 8;
        while (c < si * 8 + 7 && cum + fchunk[c] < target) { cum += fchunk[c]; c++; }
        int f = c * 4;
        while (f < c * 4 + 3 && cum + fine[f] < target) { cum += fine[f]; f++; }
        if (f >= NFINE) f = NFINE - 1;
        s_limit2 = base + ((unsigned)(f + 1) << FSHIFT);
    }
    __syncthreads();

    // compact survivors (expected ~target + O(fine-bin pop) ~ 40-80)
    unsigned limit2 = s_limit2;
    for (int i = tid; i < ncand; i += 256) {
        unsigned long long key = g_cand[i];
        if ((unsigned)(key >> 32) < limit2) {
            int p = atomicAdd(&s_cnt2, 1);
            if (p < SORT_CAP) skey[p] = key;
        }
    }
    __syncthreads();

    int cnt2 = s_cnt2;
    if (cnt2 > SORT_CAP) cnt2 = SORT_CAP;
    int sort_n = 64;
    while (sort_n < cnt2) sort_n <<= 1;
    for (int i = tid; i < sort_n; i += 256)
        if (i >= cnt2) skey[i] = ~0ull;
    __syncthreads();

    // bitonic sort ascending: key = (dist_bits<<32)|idx — matches jax top_k
    // ordering incl. lower-index-first tie-break; deterministic.
    for (int k = 2; k <= sort_n; k <<= 1) {
        for (int j = k >> 1; j > 0; j >>= 1) {
            for (int i = tid; i < sort_n; i += 256) {
                int ixj = i ^ j;
                if (ixj > i) {
                    unsigned long long a = skey[i], b = skey[ixj];
                    bool up = ((i & k) == 0);
                    if (up ? (a > b) : (a < b)) { skey[i] = b; skey[ixj] = a; }
                }
            }
            __syncthreads();
        }
    }

    if (tid < KSEL) {
        unsigned long long key = skey[tid];
        if (tid < cnt2 && key != ~0ull) {
            float d = __uint_as_float((unsigned)(key >> 32));
            w[tid] = expf(-d) / Z;
            widx[tid] = (int)(unsigned)(key & 0xffffffffu);
        } else {
            w[tid] = 0.0f;
            widx[tid] = -1;
        }
    }
    __syncthreads();

    // weighted gather of y rows
    if (DY == 64) {
        // 256 threads: (group g = tid>>6) x (dim j = tid&63); 8 k-terms each
        int j = tid & 63, g = tid >> 6;
        float acc = 0.0f;
        #pragma unroll
        for (int k = g * 8; k < g * 8 + 8; k++) {
            int id = widx[k];
            if ((unsigned)id < (unsigned)N)
                acc += w[k] * y[(size_t)id * 64 + j];
        }
        gred[tid] = acc;
        __syncthreads();
        if (tid < 64)
            out[tid] = gred[tid] + gred[64 + tid] + gred[128 + tid] + gred[192 + tid];
    } else {
        for (int j = tid; j < DY; j += blockDim.x) {
            float acc = 0.0f;
            #pragma unroll
            for (int k = 0; k < KSEL; k++) {
                int id = widx[k];
                if ((unsigned)id < (unsigned)N)
                    acc += w[k] * y[(size_t)id * DY + j];
            }
            out[j] = acc;
        }
    }

    // reset scratch for next graph replay
    for (int i = tid; i < NBINS; i += 256) g_hist[i] = 0u;
    if (tid == 0) g_ncand = 0;
}

// ---------------------------------------------------------------- host
extern "C" void kernel_launch(void* const* d_in, const int* in_sizes, int n_in,
                              void* d_out, int out_size) {
    const float* X = (const float*)d_in[0];
    const float* y = (const float*)d_in[1];
    const float* q = (const float*)d_in[2];

    int D  = in_sizes[2];
    int N  = in_sizes[0] / D;
    int DY = in_sizes[1] / N;
    float* out = (float*)d_out;

    int b1;
    if (D == 64) {
        b1 = 444;                                 // 148 SMs x 3 resident blocks
        int need = (N + 127) / 128;
        if (need < b1) b1 = need;
    } else {
        b1 = (N + 255) / 256;
        if (b1 > 444) b1 = 444;
    }
    if (b1 < 1) b1 = 1;
    if (b1 > MAXBLK) b1 = MAXBLK;

    // k_compact: 4 float4 loads per thread
    int n4 = N >> 2;
    int threads_needed = (n4 + 3) / 4;
    int b2 = (threads_needed + 255) / 256;
    if (b2 < 1) b2 = 1;

    k_dist<<<b1, 256>>>(X, q, N, D);
    k_compact<<<b2, 256>>>(N);
    k_final<<<1, 256>>>(y, out, N, DY);
}

// round 14
// speedup vs baseline: 1.4448x; 1.4448x over previous
#include <cuda_runtime.h>
#include <math.h>
#include <float.h>

#define MAXN      (1 << 20)   // dist scratch capacity (N = 1e6 fits)
#define CAND_CAP  65536
#define KSEL      32
#define NBINS     8192        // coarse bins = float_bits(d) >> 18 (monotone, d >= 0)
#define BSHIFT    18
#define FSHIFT    8           // fine bins: 256-ulp wide, 1024 per coarse bin
#define NFINE     1024
#define MAXBLK    4096
#define SORT_CAP  2048        // final bitonic capacity (u64 keys, 16 KB)

// ---- scratch (static device globals; zero-initialized at module load) ----
__device__ float              g_dist[MAXN];
__device__ float              g_partsum[MAXBLK];
__device__ unsigned           g_hist[NBINS];   // reset by k_final
__device__ float              g_Z;
__device__ int                g_bin_thresh;
__device__ int                g_ncand;         // reset by k_final
__device__ unsigned long long g_cand[CAND_CAP];
__device__ unsigned           g_done1;         // reset by k_dist last block

// ============================================================================
// Kernel 1: distances (coalesced, 16 rows/warp-iter), exp-sum partials,
// 16-bit-packed shared histogram. Last block: Z reduce + coarse threshold bin.
// ============================================================================
__global__ void k_dist(const float* __restrict__ X, const float* __restrict__ q,
                       int N, int D) {
    __shared__ unsigned hist16[NBINS / 2];   // 16 KB packed block histogram
    __shared__ float4   sq4[16];
    __shared__ float    red[256];
    __shared__ unsigned chunk[256];          // 32 coarse bins each
    __shared__ unsigned super[32];           // 8 chunks each
    __shared__ unsigned binv[32];
    __shared__ int      sel_chunk;
    __shared__ unsigned cum_at_chunk;
    __shared__ bool     amLast;

    int tid = threadIdx.x;
    for (int i = tid; i < NBINS / 2; i += 256) hist16[i] = 0u;
    if (D == 64 && tid < 16) sq4[tid] = ((const float4*)q)[tid];
    __syncthreads();

    float lsum = 0.0f;

    if (D == 64) {
        int lane = tid & 31;
        int wid  = blockIdx.x * (blockDim.x >> 5) + (tid >> 5);
        int nw   = gridDim.x * (blockDim.x >> 5);
        int col  = lane & 15;      // 16 lanes cover one 64-float row
        int half = lane >> 4;      // two rows per LDG.128
        float4 qv = sq4[col];

        for (int base = wid * 16; base < N; base += nw * 16) {
            float4 v[8];
            float  acc[8];
            #pragma unroll
            for (int u = 0; u < 8; u++) {          // 8 loads batched in flight
                int row = base + 2 * u + half;
                v[u] = qv;                          // OOB => zero diff (unused)
                if (row < N)
                    v[u] = *(const float4*)(X + (size_t)row * 64 + col * 4);
            }
            #pragma unroll
            for (int u = 0; u < 8; u++) {
                float d0 = v[u].x - qv.x, d1 = v[u].y - qv.y;
                float d2 = v[u].z - qv.z, d3 = v[u].w - qv.w;
                acc[u] = d0 * d0 + d1 * d1 + d2 * d2 + d3 * d3;
            }
            #pragma unroll
            for (int u = 0; u < 8; u++) {          // independent shfl chains
                acc[u] += __shfl_xor_sync(0xffffffffu, acc[u], 8);
                acc[u] += __shfl_xor_sync(0xffffffffu, acc[u], 4);
                acc[u] += __shfl_xor_sync(0xffffffffu, acc[u], 2);
                acc[u] += __shfl_xor_sync(0xffffffffu, acc[u], 1);
            }
            if (col == 0) {
                #pragma unroll
                for (int u = 0; u < 8; u++) {
                    int row = base + 2 * u + half;
                    if (row < N) {
                        float d = sqrtf(acc[u]);
                        g_dist[row] = d;
                        lsum += __expf(-d);         // TAU = 1
                        unsigned b = __float_as_uint(d) >> BSHIFT;
                        atomicAdd(&hist16[b >> 1], 1u << ((b & 1) * 16));
                    }
                }
            }
        }
    } else {
        for (int i = blockIdx.x * blockDim.x + tid; i < N;
             i += gridDim.x * blockDim.x) {
            float acc = 0.0f;
            const float* xr = X + (size_t)i * D;
            for (int j = 0; j < D; j++) { float d = xr[j] - q[j]; acc += d * d; }
            float d = sqrtf(acc);
            g_dist[i] = d;
            lsum += __expf(-d);
            unsigned b = __float_as_uint(d) >> BSHIFT;
            atomicAdd(&hist16[b >> 1], 1u << ((b & 1) * 16));
        }
    }

    // block Z partial (deterministic)
    red[tid] = lsum;
    __syncthreads();
    for (int s = 128; s > 0; s >>= 1) {
        if (tid < s) red[tid] += red[tid + s];
        __syncthreads();
    }
    if (tid == 0) g_partsum[blockIdx.x] = red[0];

    // flush packed histogram
    for (int i = tid; i < NBINS / 2; i += 256) {
        unsigned v = hist16[i];
        unsigned lo = v & 0xffffu, hi = v >> 16;
        if (lo) atomicAdd(&g_hist[2 * i],     lo);
        if (hi) atomicAdd(&g_hist[2 * i + 1], hi);
    }

    // ---- last-block tail ----
    __threadfence();
    if (tid == 0) amLast = (atomicAdd(&g_done1, 1u) == (unsigned)gridDim.x - 1u);
    __syncthreads();
    if (!amLast) return;

    float s2 = 0.0f;
    for (int i = tid; i < gridDim.x; i += 256) s2 += g_partsum[i];
    red[tid] = s2;
    __syncthreads();
    for (int s = 128; s > 0; s >>= 1) {
        if (tid < s) red[tid] += red[tid + s];
        __syncthreads();
    }
    if (tid == 0) g_Z = red[0];

    // 3-level coarse threshold scan: chunk(32 bins) -> super(8 chunks) -> bins
    unsigned cs = 0;
    for (int j = 0; j < 32; j++) cs += g_hist[tid * 32 + j];
    chunk[tid] = cs;
    __syncthreads();
    if (tid < 32) {
        unsigned s = 0;
        #pragma unroll
        for (int j = 0; j < 8; j++) s += chunk[tid * 8 + j];
        super[tid] = s;
    }
    __syncthreads();
    if (tid == 0) {
        unsigned target = (unsigned)(N < KSEL ? N : KSEL);
        unsigned cum = 0;
        int si = 0;
        while (si < 31 && cum + super[si] < target) { cum += super[si]; si++; }
        int c = si * 8;
        while (c < si * 8 + 7 && cum + chunk[c] < target) { cum += chunk[c]; c++; }
        sel_chunk = c;
        cum_at_chunk = cum;
    }
    __syncthreads();
    if (tid < 32) binv[tid] = g_hist[sel_chunk * 32 + tid];
    __syncthreads();
    if (tid == 0) {
        unsigned target = (unsigned)(N < KSEL ? N : KSEL);
        unsigned cum = cum_at_chunk;
        int b = sel_chunk * 32;
        int j = 0;
        while (j < 31 && cum + binv[j] < target) { cum += binv[j]; j++; b++; }
        if (b >= NBINS) b = NBINS - 1;
        g_bin_thresh = b;
        g_done1 = 0;                 // reset for next graph replay
    }
}

// ============================================================================
// Kernel 2: lean candidate compaction. 4 batched LDG.128 per thread, packed
// u64 key append. No tail code => low regs => high occupancy.
// ============================================================================
__global__ void k_compact(int N) {
    int tid = blockIdx.x * blockDim.x + threadIdx.x;
    int stride = gridDim.x * blockDim.x;
    unsigned limit = ((unsigned)(g_bin_thresh + 1)) << BSHIFT;
    const float4* d4 = (const float4*)g_dist;
    int n4 = N >> 2;

    int i0 = tid, i1 = tid + stride, i2 = tid + 2 * stride, i3 = tid + 3 * stride;
    float4 z = make_float4(FLT_MAX, FLT_MAX, FLT_MAX, FLT_MAX);
    float4 v0 = (i0 < n4) ? d4[i0] : z;
    float4 v1 = (i1 < n4) ? d4[i1] : z;
    float4 v2 = (i2 < n4) ? d4[i2] : z;
    float4 v3 = (i3 < n4) ? d4[i3] : z;

    #define CHECK(vv, ii, cc) do {                                             \
        unsigned bits_ = __float_as_uint(vv);                                  \
        if (bits_ < limit) {                                                   \
            int p_ = atomicAdd(&g_ncand, 1);                                   \
            if (p_ < CAND_CAP)                                                 \
                g_cand[p_] = ((unsigned long long)bits_ << 32) |               \
                             (unsigned)(4 * (ii) + (cc));                      \
        }                                                                      \
    } while (0)

    if (i0 < n4) { CHECK(v0.x, i0, 0); CHECK(v0.y, i0, 1); CHECK(v0.z, i0, 2); CHECK(v0.w, i0, 3); }
    if (i1 < n4) { CHECK(v1.x, i1, 0); CHECK(v1.y, i1, 1); CHECK(v1.z, i1, 2); CHECK(v1.w, i1, 3); }
    if (i2 < n4) { CHECK(v2.x, i2, 0); CHECK(v2.y, i2, 1); CHECK(v2.z, i2, 2); CHECK(v2.w, i2, 3); }
    if (i3 < n4) { CHECK(v3.x, i3, 0); CHECK(v3.y, i3, 1); CHECK(v3.z, i3, 2); CHECK(v3.w, i3, 3); }
    #undef CHECK

    if (tid == 0) {                                  // scalar tail (N % 4)
        for (int i = n4 * 4; i < N; i++) {
            unsigned bits = __float_as_uint(g_dist[i]);
            if (bits < limit) {
                int p = atomicAdd(&g_ncand, 1);
                if (p < CAND_CAP)
                    g_cand[p] = ((unsigned long long)bits << 32) | (unsigned)i;
            }
        }
    }
}

// ============================================================================
// Kernel 3: single block. Fine refinement (exact 256-ulp threshold) ->
// tiny bitonic sort -> weights/output -> scratch reset.
// ============================================================================
__global__ void k_final(const float* __restrict__ y, float* __restrict__ out,
                        int N, int DY) {
    __shared__ unsigned long long skey[SORT_CAP];   // 16 KB
    __shared__ unsigned fine[NFINE];                // 4 KB
    __shared__ unsigned fchunk[256];
    __shared__ unsigned fsuper[32];
    __shared__ int      s_below, s_cnt2;
    __shared__ unsigned s_limit2;
    __shared__ float    w[KSEL];
    __shared__ int      widx[KSEL];
    __shared__ float    gred[256];

    int tid = threadIdx.x;
    int bt = g_bin_thresh;
    float Z = g_Z;

    if (tid == 0) { s_below = 0; s_cnt2 = 0; }
    for (int i = tid; i < NFINE; i += 256) fine[i] = 0u;
    __syncthreads();

    int ncand = g_ncand;
    if (ncand > CAND_CAP) ncand = CAND_CAP;
    unsigned base = ((unsigned)bt) << BSHIFT;
    unsigned target = (unsigned)(N < KSEL ? N : KSEL);

    // fine histogram of candidates within the coarse threshold bin
    for (int i = tid; i < ncand; i += 256) {
        unsigned bits = (unsigned)(g_cand[i] >> 32);
        if (bits < base) atomicAdd((unsigned*)&s_below, 1u);
        else             atomicAdd(&fine[(bits - base) >> FSHIFT], 1u);
    }
    __syncthreads();

    // 3-level fine prefix
    fchunk[tid] = fine[tid * 4] + fine[tid * 4 + 1] +
                  fine[tid * 4 + 2] + fine[tid * 4 + 3];
    __syncthreads();
    if (tid < 32) {
        unsigned s = 0;
        #pragma unroll
        for (int j = 0; j < 8; j++) s += fchunk[tid * 8 + j];
        fsuper[tid] = s;
    }
    __syncthreads();
    if (tid == 0) {
        unsigned cum = (unsigned)s_below;
        int si = 0;
        while (si < 31 && cum + fsuper[si] < target) { cum += fsuper[si]; si++; }
        int c = si * 8;
        while (c < si * 8 + 7 && cum + fchunk[c] < target) { cum += fchunk[c]; c++; }
        int f = c * 4;
        while (f < c * 4 + 3 && cum + fine[f] < target) { cum += fine[f]; f++; }
        if (f >= NFINE) f = NFINE - 1;
        s_limit2 = base + ((unsigned)(f + 1) << FSHIFT);
    }
    __syncthreads();

    // compact survivors (expected ~target + O(fine-bin pop) ~ 40-80)
    unsigned limit2 = s_limit2;
    for (int i = tid; i < ncand; i += 256) {
        unsigned long long key = g_cand[i];
        if ((unsigned)(key >> 32) < limit2) {
            int p = atomicAdd(&s_cnt2, 1);
            if (p < SORT_CAP) skey[p] = key;
        }
    }
    __syncthreads();

    int cnt2 = s_cnt2;
    if (cnt2 > SORT_CAP) cnt2 = SORT_CAP;
    int sort_n = 64;
    while (sort_n < cnt2) sort_n <<= 1;
    for (int i = tid; i < sort_n; i += 256)
        if (i >= cnt2) skey[i] = ~0ull;
    __syncthreads();

    // bitonic sort ascending: key = (dist_bits<<32)|idx — matches jax top_k
    // ordering incl. lower-index-first tie-break; deterministic.
    for (int k = 2; k <= sort_n; k <<= 1) {
        for (int j = k >> 1; j > 0; j >>= 1) {
            for (int i = tid; i < sort_n; i += 256) {
                int ixj = i ^ j;
                if (ixj > i) {
                    unsigned long long a = skey[i], b = skey[ixj];
                    bool up = ((i & k) == 0);
                    if (up ? (a > b) : (a < b)) { skey[i] = b; skey[ixj] = a; }
                }
            }
            __syncthreads();
        }
    }

    if (tid < KSEL) {
        unsigned long long key = skey[tid];
        if (tid < cnt2 && key != ~0ull) {
            float d = __uint_as_float((unsigned)(key >> 32));
            w[tid] = expf(-d) / Z;   // full-precision expf on the 32 that matter
            widx[tid] = (int)(unsigned)(key & 0xffffffffu);
        } else {
            w[tid] = 0.0f;
            widx[tid] = -1;
        }
    }
    __syncthreads();

    // weighted gather of y rows
    if (DY == 64) {
        // 256 threads: (group g = tid>>6) x (dim j = tid&63); 8 k-terms each
        int j = tid & 63, g = tid >> 6;
        float acc = 0.0f;
        #pragma unroll
        for (int k = g * 8; k < g * 8 + 8; k++) {
            int id = widx[k];
            if ((unsigned)id < (unsigned)N)
                acc += w[k] * y[(size_t)id * 64 + j];
        }
        gred[tid] = acc;
        __syncthreads();
        if (tid < 64)
            out[tid] = gred[tid] + gred[64 + tid] + gred[128 + tid] + gred[192 + tid];
    } else {
        for (int j = tid; j < DY; j += blockDim.x) {
            float acc = 0.0f;
            #pragma unroll
            for (int k = 0; k < KSEL; k++) {
                int id = widx[k];
                if ((unsigned)id < (unsigned)N)
                    acc += w[k] * y[(size_t)id * DY + j];
            }
            out[j] = acc;
        }
    }

    // reset scratch for next graph replay
    for (int i = tid; i < NBINS; i += 256) g_hist[i] = 0u;
    if (tid == 0) g_ncand = 0;
}

// ---------------------------------------------------------------- host
extern "C" void kernel_launch(void* const* d_in, const int* in_sizes, int n_in,
                              void* d_out, int out_size) {
    const float* X = (const float*)d_in[0];
    const float* y = (const float*)d_in[1];
    const float* q = (const float*)d_in[2];

    int D  = in_sizes[2];
    int N  = in_sizes[0] / D;
    int DY = in_sizes[1] / N;
    float* out = (float*)d_out;

    int b1;
    if (D == 64) {
        b1 = 1184;                                // 148 SMs x 8 blocks (64 warps/SM)
        int need = (N + 127) / 128;
        if (need < b1) b1 = need;
    } else {
        b1 = (N + 255) / 256;
        if (b1 > 1184) b1 = 1184;
    }
    if (b1 < 1) b1 = 1;
    if (b1 > MAXBLK) b1 = MAXBLK;

    // k_compact: 4 float4 loads per thread
    int n4 = N >> 2;
    int threads_needed = (n4 + 3) / 4;
    int b2 = (threads_needed + 255) / 256;
    if (b2 < 1) b2 = 1;

    k_dist<<<b1, 256>>>(X, q, N, D);
    k_compact<<<b2, 256>>>(N);
    k_final<<<1, 256>>>(y, out, N, DY);
}

// round 16
// speedup vs baseline: 1.5430x; 1.0680x over previous
#include <cuda_runtime.h>
#include <math.h>
#include <float.h>

#define MAXN      (1 << 20)   // dist scratch capacity (N = 1e6 fits)
#define CAND_CAP  65536
#define KSEL      32
#define NBINS     8192        // coarse bins = float_bits(d) >> 18 (monotone, d >= 0)
#define BSHIFT    18
#define FSHIFT    8           // fine bins: 256-ulp wide, 1024 per coarse bin
#define NFINE     1024
#define MAXBLK    4096
#define SORT_CAP  2048        // final bitonic capacity (u64 keys, 16 KB)

// ---- scratch (static device globals; zero-initialized at module load) ----
__device__ float              g_dist[MAXN];
__device__ float              g_partsum[MAXBLK];
__device__ unsigned           g_hist[NBINS];   // reset by k_final
__device__ float              g_Z;
__device__ int                g_bin_thresh;
__device__ int                g_ncand;         // reset by k_final
__device__ unsigned long long g_cand[CAND_CAP];
__device__ unsigned           g_done1;         // reset by k_dist last block

// ============================================================================
// Kernel 1: distances (coalesced, 16 rows/warp-iter). Recursive-halving
// shfl reduce leaves each row's total on a distinct lane => the sqrt/exp/
// store/hist epilogue is ONE warp-instruction each per 16 rows (16 active
// lanes) instead of 16 two-lane-serialized instructions.
// Last block: Z reduce + coarse threshold bin.
// ============================================================================
__global__ void k_dist(const float* __restrict__ X, const float* __restrict__ q,
                       int N, int D) {
    __shared__ unsigned hist16[NBINS / 2];   // 16 KB packed block histogram
    __shared__ float4   sq4[16];
    __shared__ float    red[256];
    __shared__ unsigned chunk[256];          // 32 coarse bins each
    __shared__ unsigned super[32];           // 8 chunks each
    __shared__ unsigned binv[32];
    __shared__ int      sel_chunk;
    __shared__ unsigned cum_at_chunk;
    __shared__ bool     amLast;

    int tid = threadIdx.x;
    for (int i = tid; i < NBINS / 2; i += 256) hist16[i] = 0u;
    if (D == 64 && tid < 16) sq4[tid] = ((const float4*)q)[tid];
    __syncthreads();

    float lsum = 0.0f;

    if (D == 64) {
        int lane = tid & 31;
        int wid  = blockIdx.x * (blockDim.x >> 5) + (tid >> 5);
        int nw   = gridDim.x * (blockDim.x >> 5);
        int col  = lane & 15;      // 16 lanes cover one 64-float row
        int half = lane >> 4;      // two rows per LDG.128
        float4 qv = sq4[col];
        // lane-owned reg index after the tree reduce:
        // u = bit3(col)*4 + bit2(col)*2 + bit1(col); pairs (col, col^1) duplicate
        int uown  = ((col >> 3) & 1) * 4 + ((col >> 2) & 1) * 2 + ((col >> 1) & 1);
        bool actor = ((col & 1) == 0);

        for (int base = wid * 16; base < N; base += nw * 16) {
            float4 v[8];
            float  a[8];
            #pragma unroll
            for (int u = 0; u < 8; u++) {          // 8 loads batched in flight
                int row = base + 2 * u + half;
                v[u] = qv;                          // OOB => zero diff (unused)
                if (row < N)
                    v[u] = *(const float4*)(X + (size_t)row * 64 + col * 4);
            }
            #pragma unroll
            for (int u = 0; u < 8; u++) {
                float d0 = v[u].x - qv.x, d1 = v[u].y - qv.y;
                float d2 = v[u].z - qv.z, d3 = v[u].w - qv.w;
                a[u] = d0 * d0 + d1 * d1 + d2 * d2 + d3 * d3;
            }

            // recursive halving over the 16 col-lanes (masks stay within the
            // 16-lane half): 8 shfl per 16 rows; row totals land distributed.
            float b4[4];
            #pragma unroll
            for (int u = 0; u < 4; u++) {
                float sent = (col & 8) ? a[u] : a[u + 4];
                float got  = __shfl_xor_sync(0xffffffffu, sent, 8);
                float kept = (col & 8) ? a[u + 4] : a[u];
                b4[u] = kept + got;
            }
            float c2[2];
            #pragma unroll
            for (int u = 0; u < 2; u++) {
                float sent = (col & 4) ? b4[u] : b4[u + 2];
                float got  = __shfl_xor_sync(0xffffffffu, sent, 4);
                float kept = (col & 4) ? b4[u + 2] : b4[u];
                c2[u] = kept + got;
            }
            {
                float sent = (col & 2) ? c2[0] : c2[1];
                float got  = __shfl_xor_sync(0xffffffffu, sent, 2);
                float kept = (col & 2) ? c2[1] : c2[0];
                float e = kept + got;
                e += __shfl_xor_sync(0xffffffffu, e, 1);

                int row = base + 2 * uown + half;
                if (actor && row < N) {
                    float d = sqrtf(e);
                    g_dist[row] = d;
                    lsum += __expf(-d);             // TAU = 1
                    unsigned b = __float_as_uint(d) >> BSHIFT;
                    atomicAdd(&hist16[b >> 1], 1u << ((b & 1) * 16));
                }
            }
        }
    } else {
        for (int i = blockIdx.x * blockDim.x + tid; i < N;
             i += gridDim.x * blockDim.x) {
            float acc = 0.0f;
            const float* xr = X + (size_t)i * D;
            for (int j = 0; j < D; j++) { float d = xr[j] - q[j]; acc += d * d; }
            float d = sqrtf(acc);
            g_dist[i] = d;
            lsum += __expf(-d);
            unsigned b = __float_as_uint(d) >> BSHIFT;
            atomicAdd(&hist16[b >> 1], 1u << ((b & 1) * 16));
        }
    }

    // block Z partial (deterministic: fixed per-thread ownership + fixed tree)
    red[tid] = lsum;
    __syncthreads();
    for (int s = 128; s > 0; s >>= 1) {
        if (tid < s) red[tid] += red[tid + s];
        __syncthreads();
    }
    if (tid == 0) g_partsum[blockIdx.x] = red[0];

    // flush packed histogram
    for (int i = tid; i < NBINS / 2; i += 256) {
        unsigned v = hist16[i];
        unsigned lo = v & 0xffffu, hi = v >> 16;
        if (lo) atomicAdd(&g_hist[2 * i],     lo);
        if (hi) atomicAdd(&g_hist[2 * i + 1], hi);
    }

    // ---- last-block tail ----
    __threadfence();
    if (tid == 0) amLast = (atomicAdd(&g_done1, 1u) == (unsigned)gridDim.x - 1u);
    __syncthreads();
    if (!amLast) return;

    float s2 = 0.0f;
    for (int i = tid; i < gridDim.x; i += 256) s2 += g_partsum[i];
    red[tid] = s2;
    __syncthreads();
    for (int s = 128; s > 0; s >>= 1) {
        if (tid < s) red[tid] += red[tid + s];
        __syncthreads();
    }
    if (tid == 0) g_Z = red[0];

    // 3-level coarse threshold scan: chunk(32 bins) -> super(8 chunks) -> bins
    unsigned cs = 0;
    for (int j = 0; j < 32; j++) cs += g_hist[tid * 32 + j];
    chunk[tid] = cs;
    __syncthreads();
    if (tid < 32) {
        unsigned s = 0;
        #pragma unroll
        for (int j = 0; j < 8; j++) s += chunk[tid * 8 + j];
        super[tid] = s;
    }
    __syncthreads();
    if (tid == 0) {
        unsigned target = (unsigned)(N < KSEL ? N : KSEL);
        unsigned cum = 0;
        int si = 0;
        while (si < 31 && cum + super[si] < target) { cum += super[si]; si++; }
        int c = si * 8;
        while (c < si * 8 + 7 && cum + chunk[c] < target) { cum += chunk[c]; c++; }
        sel_chunk = c;
        cum_at_chunk = cum;
    }
    __syncthreads();
    if (tid < 32) binv[tid] = g_hist[sel_chunk * 32 + tid];
    __syncthreads();
    if (tid == 0) {
        unsigned target = (unsigned)(N < KSEL ? N : KSEL);
        unsigned cum = cum_at_chunk;
        int b = sel_chunk * 32;
        int j = 0;
        while (j < 31 && cum + binv[j] < target) { cum += binv[j]; j++; b++; }
        if (b >= NBINS) b = NBINS - 1;
        g_bin_thresh = b;
        g_done1 = 0;                 // reset for next graph replay
    }
}

// ============================================================================
// Kernel 2: lean candidate compaction. 4 batched LDG.128 per thread, packed
// u64 key append. No tail code => low regs => high occupancy.
// ============================================================================
__global__ void k_compact(int N) {
    int tid = blockIdx.x * blockDim.x + threadIdx.x;
    int stride = gridDim.x * blockDim.x;
    unsigned limit = ((unsigned)(g_bin_thresh + 1)) << BSHIFT;
    const float4* d4 = (const float4*)g_dist;
    int n4 = N >> 2;

    int i0 = tid, i1 = tid + stride, i2 = tid + 2 * stride, i3 = tid + 3 * stride;
    float4 z = make_float4(FLT_MAX, FLT_MAX, FLT_MAX, FLT_MAX);
    float4 v0 = (i0 < n4) ? d4[i0] : z;
    float4 v1 = (i1 < n4) ? d4[i1] : z;
    float4 v2 = (i2 < n4) ? d4[i2] : z;
    float4 v3 = (i3 < n4) ? d4[i3] : z;

    #define CHECK(vv, ii, cc) do {                                             \
        unsigned bits_ = __float_as_uint(vv);                                  \
        if (bits_ < limit) {                                                   \
            int p_ = atomicAdd(&g_ncand, 1);                                   \
            if (p_ < CAND_CAP)                                                 \
                g_cand[p_] = ((unsigned long long)bits_ << 32) |               \
                             (unsigned)(4 * (ii) + (cc));                      \
        }                                                                      \
    } while (0)

    if (i0 < n4) { CHECK(v0.x, i0, 0); CHECK(v0.y, i0, 1); CHECK(v0.z, i0, 2); CHECK(v0.w, i0, 3); }
    if (i1 < n4) { CHECK(v1.x, i1, 0); CHECK(v1.y, i1, 1); CHECK(v1.z, i1, 2); CHECK(v1.w, i1, 3); }
    if (i2 < n4) { CHECK(v2.x, i2, 0); CHECK(v2.y, i2, 1); CHECK(v2.z, i2, 2); CHECK(v2.w, i2, 3); }
    if (i3 < n4) { CHECK(v3.x, i3, 0); CHECK(v3.y, i3, 1); CHECK(v3.z, i3, 2); CHECK(v3.w, i3, 3); }
    #undef CHECK

    if (tid == 0) {                                  // scalar tail (N % 4)
        for (int i = n4 * 4; i < N; i++) {
            unsigned bits = __float_as_uint(g_dist[i]);
            if (bits < limit) {
                int p = atomicAdd(&g_ncand, 1);
                if (p < CAND_CAP)
                    g_cand[p] = ((unsigned long long)bits << 32) | (unsigned)i;
            }
        }
    }
}

// ============================================================================
// Kernel 3: single block. Fine refinement (exact 256-ulp threshold) ->
// tiny bitonic sort -> weights/output -> scratch reset.
// ============================================================================
__global__ void k_final(const float* __restrict__ y, float* __restrict__ out,
                        int N, int DY) {
    __shared__ unsigned long long skey[SORT_CAP];   // 16 KB
    __shared__ unsigned fine[NFINE];                // 4 KB
    __shared__ unsigned fchunk[256];
    __shared__ unsigned fsuper[32];
    __shared__ int      s_below, s_cnt2;
    __shared__ unsigned s_limit2;
    __shared__ float    w[KSEL];
    __shared__ int      widx[KSEL];
    __shared__ float    gred[256];

    int tid = threadIdx.x;
    int bt = g_bin_thresh;
    float Z = g_Z;

    if (tid == 0) { s_below = 0; s_cnt2 = 0; }
    for (int i = tid; i < NFINE; i += 256) fine[i] = 0u;
    __syncthreads();

    int ncand = g_ncand;
    if (ncand > CAND_CAP) ncand = CAND_CAP;
    unsigned base = ((unsigned)bt) << BSHIFT;
    unsigned target = (unsigned)(N < KSEL ? N : KSEL);

    // fine histogram of candidates within the coarse threshold bin
    for (int i = tid; i < ncand; i += 256) {
        unsigned bits = (unsigned)(g_cand[i] >> 32);
        if (bits < base) atomicAdd((unsigned*)&s_below, 1u);
        else             atomicAdd(&fine[(bits - base) >> FSHIFT], 1u);
    }
    __syncthreads();

    // 3-level fine prefix
    fchunk[tid] = fine[tid * 4] + fine[tid * 4 + 1] +
                  fine[tid * 4 + 2] + fine[tid * 4 + 3];
    __syncthreads();
    if (tid < 32) {
        unsigned s = 0;
        #pragma unroll
        for (int j = 0; j < 8; j++) s += fchunk[tid * 8 + j];
        fsuper[tid] = s;
    }
    __syncthreads();
    if (tid == 0) {
        unsigned cum = (unsigned)s_below;
        int si = 0;
        while (si < 31 && cum + fsuper[si] < target) { cum += fsuper[si]; si++; }
        int c = si * 8;
        while (c < si * 8 + 7 && cum + fchunk[c] < target) { cum += fchunk[c]; c++; }
        int f = c * 4;
        while (f < c * 4 + 3 && cum + fine[f] < target) { cum += fine[f]; f++; }
        if (f >= NFINE) f = NFINE - 1;
        s_limit2 = base + ((unsigned)(f + 1) << FSHIFT);
    }
    __syncthreads();

    // compact survivors (expected ~target + O(fine-bin pop) ~ 40-80)
    unsigned limit2 = s_limit2;
    for (int i = tid; i < ncand; i += 256) {
        unsigned long long key = g_cand[i];
        if ((unsigned)(key >> 32) < limit2) {
            int p = atomicAdd(&s_cnt2, 1);
            if (p < SORT_CAP) skey[p] = key;
        }
    }
    __syncthreads();

    int cnt2 = s_cnt2;
    if (cnt2 > SORT_CAP) cnt2 = SORT_CAP;
    int sort_n = 64;
    while (sort_n < cnt2) sort_n <<= 1;
    for (int i = tid; i < sort_n; i += 256)
        if (i >= cnt2) skey[i] = ~0ull;
    __syncthreads();

    // bitonic sort ascending: key = (dist_bits<<32)|idx — matches jax top_k
    // ordering incl. lower-index-first tie-break; deterministic.
    for (int k = 2; k <= sort_n; k <<= 1) {
        for (int j = k >> 1; j > 0; j >>= 1) {
            for (int i = tid; i < sort_n; i += 256) {
                int ixj = i ^ j;
                if (ixj > i) {
                    unsigned long long a = skey[i], b = skey[ixj];
                    bool up = ((i & k) == 0);
                    if (up ? (a > b) : (a < b)) { skey[i] = b; skey[ixj] = a; }
                }
            }
            __syncthreads();
        }
    }

    if (tid < KSEL) {
        unsigned long long key = skey[tid];
        if (tid < cnt2 && key != ~0ull) {
            float d = __uint_as_float((unsigned)(key >> 32));
            w[tid] = expf(-d) / Z;   // full-precision expf on the 32 that matter
            widx[tid] = (int)(unsigned)(key & 0xffffffffu);
        } else {
            w[tid] = 0.0f;
            widx[tid] = -1;
        }
    }
    __syncthreads();

    // weighted gather of y rows
    if (DY == 64) {
        // 256 threads: (group g = tid>>6) x (dim j = tid&63); 8 k-terms each
        int j = tid & 63, g = tid >> 6;
        float acc = 0.0f;
        #pragma unroll
        for (int k = g * 8; k < g * 8 + 8; k++) {
            int id = widx[k];
            if ((unsigned)id < (unsigned)N)
                acc += w[k] * y[(size_t)id * 64 + j];
        }
        gred[tid] = acc;
        __syncthreads();
        if (tid < 64)
            out[tid] = gred[tid] + gred[64 + tid] + gred[128 + tid] + gred[192 + tid];
    } else {
        for (int j = tid; j < DY; j += blockDim.x) {
            float acc = 0.0f;
            #pragma unroll
            for (int k = 0; k < KSEL; k++) {
                int id = widx[k];
                if ((unsigned)id < (unsigned)N)
                    acc += w[k] * y[(size_t)id * DY + j];
            }
            out[j] = acc;
        }
    }

    // reset scratch for next graph replay
    for (int i = tid; i < NBINS; i += 256) g_hist[i] = 0u;
    if (tid == 0) g_ncand = 0;
}

// ---------------------------------------------------------------- host
extern "C" void kernel_launch(void* const* d_in, const int* in_sizes, int n_in,
                              void* d_out, int out_size) {
    const float* X = (const float*)d_in[0];
    const float* y = (const float*)d_in[1];
    const float* q = (const float*)d_in[2];

    int D  = in_sizes[2];
    int N  = in_sizes[0] / D;
    int DY = in_sizes[1] / N;
    float* out = (float*)d_out;

    int b1;
    if (D == 64) {
        b1 = 1184;                                // 148 SMs x 8 blocks (64 warps/SM)
        int need = (N + 127) / 128;
        if (need < b1) b1 = need;
    } else {
        b1 = (N + 255) / 256;
        if (b1 > 1184) b1 = 1184;
    }
    if (b1 < 1) b1 = 1;
    if (b1 > MAXBLK) b1 = MAXBLK;

    // k_compact: 4 float4 loads per thread
    int n4 = N >> 2;
    int threads_needed = (n4 + 3) / 4;
    int b2 = (threads_needed + 255) / 256;
    if (b2 < 1) b2 = 1;

    k_dist<<<b1, 256>>>(X, q, N, D);
    k_compact<<<b2, 256>>>(N);
    k_final<<<1, 256>>>(y, out, N, DY);
}